// round 12
// baseline (speedup 1.0000x reference)
#include <cuda_runtime.h>
#include <cuda_bf16.h>
#include <math.h>
#include <stdint.h>

#define BATCH 2048
#define LSEQ  70
#define DIN   15
#define HID   16
#define NF    4
#define KW    40
#define CDIM  20          // DIN + 1 + NF
#define LP    31          // LSEQ - KW + 1
#define Z0    64
#define NOUT  128         // 2*Z0
#define SIGCH 8420        // C + C^2 + C^3

#define KTOT   8640       // padded K (zero tail), 9*960
#define KSPLIT 9
#define KCHUNK 960
#define KB     32         // k per pipeline stage (bf16 elems)
#define NKT    (KCHUNK / KB)        // 30 iterations (single pass, all 3 terms)

typedef unsigned long long ull;

// Scratch (static device arrays; zero-initialized at load — padded K tail
// [8420,8640) is never written and stays zero)
__device__ __nv_bfloat16 g_a0[(size_t)BATCH * KTOT];   // sig hi
__device__ __nv_bfloat16 g_a1[(size_t)BATCH * KTOT];   // sig lo
__device__ __nv_bfloat16 g_b0[(size_t)NOUT * KTOT];    // wout hi
__device__ __nv_bfloat16 g_b1[(size_t)NOUT * KTOT];    // wout lo
__device__ float g_zpart[(size_t)KSPLIT * BATCH * NOUT];

// ---------------------------------------------------------------------------
// helpers
// ---------------------------------------------------------------------------
__device__ __forceinline__ uint32_t smem_u32(const void* p) {
    uint32_t a;
    asm("{ .reg .u64 t; cvta.to.shared.u64 t, %1; cvt.u32.u64 %0, t; }"
        : "=r"(a) : "l"(p));
    return a;
}
// 64B rows, 16B segs swizzled by seg ^ ((row>>1)&3)
__device__ __forceinline__ uint32_t swadr(uint32_t base, int row, int off) {
    return base + row * 64 + ((((off >> 4) ^ (row >> 1)) & 3) << 4) + (off & 15);
}
#define CPA16(dst, src) \
    asm volatile("cp.async.cg.shared.global [%0], [%1], 16;" :: "r"(dst), "l"(src))
#define CPA_COMMIT() asm volatile("cp.async.commit_group;" ::: "memory")
#define CPA_WAIT0()  asm volatile("cp.async.wait_group 0;" ::: "memory")
#define CPA_WAIT1()  asm volatile("cp.async.wait_group 1;" ::: "memory")

#define MMA16816(d, a, b) \
    asm volatile("mma.sync.aligned.m16n8k16.row.col.f32.bf16.bf16.f32 " \
        "{%0,%1,%2,%3}, {%4,%5,%6,%7}, {%8,%9}, {%0,%1,%2,%3};" \
        : "+f"((d)[0]), "+f"((d)[1]), "+f"((d)[2]), "+f"((d)[3]) \
        : "r"((a)[0]), "r"((a)[1]), "r"((a)[2]), "r"((a)[3]), \
          "r"((b)[0]), "r"((b)[1]))

#define LDSM4(r, addr) \
    asm volatile("ldmatrix.sync.aligned.m8n8.x4.shared.b16 {%0,%1,%2,%3}, [%4];" \
        : "=r"((r)[0]), "=r"((r)[1]), "=r"((r)[2]), "=r"((r)[3]) : "r"(addr))

// ---------------------------------------------------------------------------
// Kernel 1: per-batch path (conv chain) + depth-3 signature.
// 512 threads/block: conv1 on warps 0-3 (proven sliding window), scan on
// 400 threads with ONE (i,j) pair each (20 accs -> low regs, 12.5 warps).
// ---------------------------------------------------------------------------
__global__ __launch_bounds__(512, 2) void sig_kernel(
    const float* __restrict__ x,    // (B, L, DIN)
    const float* __restrict__ w1,   // (HID, DIN, KW)
    const float* __restrict__ b1,
    const float* __restrict__ w2,   // (HID, HID)
    const float* __restrict__ b2,
    const float* __restrict__ w3,   // (NF, HID)
    const float* __restrict__ b3)
{
    __shared__ float xs[(LSEQ + 1) * DIN];
    __shared__ float h1s[HID * LP];
    __shared__ float paths[LP * CDIM];
    __shared__ float h2s[HID * LP];
    __shared__ __align__(16) float dsm[LP * CDIM];
    __shared__ __align__(16) float w1s[HID * DIN * KW];  // 38.4 KB

    const int b = blockIdx.x;
    const int t = threadIdx.x;

    for (int i = t; i < LSEQ * DIN; i += 512) xs[i] = x[(size_t)b * LSEQ * DIN + i];
    if (t < DIN) xs[LSEQ * DIN + t] = 0.f;
    {
        const float4* w4 = (const float4*)w1;
        float4* s4 = (float4*)w1s;
        for (int i = t; i < HID * DIN * KW / 4; i += 512) s4[i] = w4[i];
    }
    __syncthreads();

    // ---- conv1 (VALID, kernel 40): 128 threads, sliding window ----
    if (t < 128) {
        const int o  = t >> 3;
        const int l0 = (t & 7) * 4;
        float a0 = 0.f, a1 = 0.f, a2 = 0.f, a3 = 0.f;
        const float* wrow = &w1s[o * DIN * KW];
        #pragma unroll 1
        for (int c = 0; c < DIN; ++c) {
            float xw0 = xs[(l0 + 0) * DIN + c];
            float xw1 = xs[(l0 + 1) * DIN + c];
            float xw2 = xs[(l0 + 2) * DIN + c];
            const float4* wc4 = (const float4*)(wrow + c * KW);
            #pragma unroll
            for (int kq = 0; kq < KW / 4; ++kq) {
                float4 w4 = wc4[kq];
                float xw3;
                xw3 = xs[(l0 + 4*kq + 3) * DIN + c];
                a0 = fmaf(w4.x, xw0, a0); a1 = fmaf(w4.x, xw1, a1);
                a2 = fmaf(w4.x, xw2, a2); a3 = fmaf(w4.x, xw3, a3);
                xw0 = xw1; xw1 = xw2; xw2 = xw3;
                xw3 = xs[(l0 + 4*kq + 4) * DIN + c];
                a0 = fmaf(w4.y, xw0, a0); a1 = fmaf(w4.y, xw1, a1);
                a2 = fmaf(w4.y, xw2, a2); a3 = fmaf(w4.y, xw3, a3);
                xw0 = xw1; xw1 = xw2; xw2 = xw3;
                xw3 = xs[(l0 + 4*kq + 5) * DIN + c];
                a0 = fmaf(w4.z, xw0, a0); a1 = fmaf(w4.z, xw1, a1);
                a2 = fmaf(w4.z, xw2, a2); a3 = fmaf(w4.z, xw3, a3);
                xw0 = xw1; xw1 = xw2; xw2 = xw3;
                xw3 = xs[(l0 + 4*kq + 6) * DIN + c];
                a0 = fmaf(w4.w, xw0, a0); a1 = fmaf(w4.w, xw1, a1);
                a2 = fmaf(w4.w, xw2, a2); a3 = fmaf(w4.w, xw3, a3);
                xw0 = xw1; xw1 = xw2; xw2 = xw3;
            }
        }
        float bias = b1[o];
        if (l0 + 0 < LP) h1s[o * LP + l0 + 0] = fmaxf(a0 + bias, 0.f);
        if (l0 + 1 < LP) h1s[o * LP + l0 + 1] = fmaxf(a1 + bias, 0.f);
        if (l0 + 2 < LP) h1s[o * LP + l0 + 2] = fmaxf(a2 + bias, 0.f);
        if (l0 + 3 < LP) h1s[o * LP + l0 + 3] = fmaxf(a3 + bias, 0.f);
    }
    __syncthreads();

    // ---- conv2 (1x1) + relu ----
    if (t < HID * LP) {
        int o = t / LP, l = t % LP;
        float s = b2[o];
        #pragma unroll
        for (int c2 = 0; c2 < HID; ++c2)
            s = fmaf(w2[o * HID + c2], h1s[c2 * LP + l], s);
        h2s[t] = fmaxf(s, 0.f);
    }
    __syncthreads();

    // ---- conv3 (1x1) + assemble path ----
    for (int idx = t; idx < LP * CDIM; idx += 512) {
        int l = idx / CDIM, c = idx % CDIM;
        float v;
        if (c < DIN) {
            v = xs[(KW - 1 + l) * DIN + c];
        } else if (c == DIN) {
            v = (float)l * (1.0f / (LP - 1));
        } else {
            int f = c - DIN - 1;
            float s = b3[f];
            #pragma unroll
            for (int c2 = 0; c2 < HID; ++c2)
                s = fmaf(w3[f * HID + c2], h2s[c2 * LP + l], s);
            v = s;
        }
        paths[idx] = v;
    }
    __syncthreads();

    for (int idx = t; idx < LP * CDIM; idx += 512) {
        int l = idx / CDIM;
        dsm[idx] = paths[idx] - (l ? paths[idx - CDIM] : 0.f);
    }
    __syncthreads();

    // ---- depth-3 signature (Chen), barrier-free scan: one (i,j)/thread ----
    const int i0 = t / CDIM;     // 0..19 for t<400
    const int j0 = t % CDIM;
    float s1 = 0.f, s2 = 0.f;
    float s3[CDIM];
    #pragma unroll
    for (int k = 0; k < CDIM; ++k) s3[k] = 0.f;

    if (t < 400) {
        #pragma unroll 2
        for (int s = 0; s < LP; ++s) {
            const float* dr = &dsm[s * CDIM];
            float dj = dr[j0];
            float di = dr[i0];
            float A  = fmaf(dj, fmaf(di, 1.f / 6.f, 0.5f * s1), s2);
            s2 = fmaf(dj, fmaf(di, 0.5f, s1), s2);
            s1 += di;
            const float4* dv4 = (const float4*)dr;
            #pragma unroll
            for (int q = 0; q < 5; ++q) {
                float4 dv = dv4[q];
                s3[q*4+0] = fmaf(A, dv.x, s3[q*4+0]);
                s3[q*4+1] = fmaf(A, dv.y, s3[q*4+1]);
                s3[q*4+2] = fmaf(A, dv.z, s3[q*4+2]);
                s3[q*4+3] = fmaf(A, dv.w, s3[q*4+3]);
            }
        }
    }

    // ---- write signature as bf16 hi/lo: [s1(20) | s2(400) | s3(8000)] ----
    size_t base = (size_t)b * KTOT;
    if (t < CDIM) {
        float v = paths[(LP - 1) * CDIM + t];      // s1 telescopes
        __nv_bfloat16 h = __float2bfloat16_rn(v);
        g_a0[base + t] = h;
        g_a1[base + t] = __float2bfloat16_rn(v - __bfloat162float(h));
    }
    if (t < 400) {
        {
            __nv_bfloat16 h = __float2bfloat16_rn(s2);
            g_a0[base + CDIM + t] = h;
            g_a1[base + CDIM + t] = __float2bfloat16_rn(s2 - __bfloat162float(h));
        }
        size_t r0 = base + 420 + (size_t)t * CDIM;
        #pragma unroll
        for (int q = 0; q < 5; ++q) {
            ull h0 = 0, l0p = 0;
            #pragma unroll
            for (int j = 0; j < 4; ++j) {
                float va = s3[q*4+j];
                __nv_bfloat16 h = __float2bfloat16_rn(va);
                __nv_bfloat16 l = __float2bfloat16_rn(va - __bfloat162float(h));
                h0  |= (ull)__bfloat16_as_ushort(h) << (16 * j);
                l0p |= (ull)__bfloat16_as_ushort(l) << (16 * j);
            }
            *(ull*)&g_a0[r0 + q * 4] = h0;
            *(ull*)&g_a1[r0 + q * 4] = l0p;
        }
    }
}

// ---------------------------------------------------------------------------
// Kernel 1b: wout -> bf16 hi/lo split (padded to KTOT)
// ---------------------------------------------------------------------------
__global__ __launch_bounds__(256) void wconv_kernel(const float* __restrict__ wout)
{
    int i = blockIdx.x * 256 + threadIdx.x;
    if (i >= NOUT * SIGCH) return;
    int n = i / SIGCH, k = i % SIGCH;
    float v = wout[i];
    __nv_bfloat16 h = __float2bfloat16_rn(v);
    g_b0[(size_t)n * KTOT + k] = h;
    g_b1[(size_t)n * KTOT + k] = __float2bfloat16_rn(v - __bfloat162float(h));
}

// ---------------------------------------------------------------------------
// Kernel 2: mma.sync bf16 3-term GEMM, single pass over K. (proven R11)
// grid (16, 9): 128x128 block tile, 8 warps (warp tile 32x64).
// ---------------------------------------------------------------------------
#define STAGE_SZ 32768
#define GEMM_SMEM (2 * STAGE_SZ)

__global__ __launch_bounds__(256) void mma_gemm()
{
    extern __shared__ __align__(128) char smem[];
    const uint32_t sb = smem_u32(smem);

    const int t    = threadIdx.x;
    const int wid  = t >> 5;
    const int lane = t & 31;
    const int lr   = lane >> 2;       // 0..7
    const int lc   = lane & 3;        // 0..3
    const int mw   = (wid & 3) * 32;  // warp m offset
    const int nw   = (wid >> 2) * 64; // warp n offset
    const int m0   = blockIdx.x * 128;
    const int kz   = blockIdx.y;
    const int kbase = kz * KCHUNK;

    float acc[2][8][4];
    #pragma unroll
    for (int i = 0; i < 2; ++i)
        #pragma unroll
        for (int j = 0; j < 8; ++j)
            #pragma unroll
            for (int c = 0; c < 4; ++c) acc[i][j][c] = 0.f;

    #define FILL(bsel, kt)                                                     \
        {                                                                      \
            int k0 = kbase + (kt) * KB;                                        \
            uint32_t stg = sb + (uint32_t)(bsel) * STAGE_SZ;                   \
            _Pragma("unroll")                                                  \
            for (int i = 0; i < 8; ++i) {                                      \
                int id = t + i * 256;                                          \
                int sub = id >> 9, w = id & 511;                               \
                int row = w >> 2, seg = w & 3;                                 \
                uint32_t dst = stg + sub * 8192 + row * 64                     \
                               + ((seg ^ ((row >> 1) & 3)) << 4);              \
                const __nv_bfloat16* src;                                      \
                if (sub == 0)      src = g_a0 + (size_t)(m0 + row) * KTOT;     \
                else if (sub == 1) src = g_a1 + (size_t)(m0 + row) * KTOT;     \
                else if (sub == 2) src = g_b0 + (size_t)row * KTOT;            \
                else               src = g_b1 + (size_t)row * KTOT;            \
                CPA16(dst, (const char*)(src + k0 + seg * 8));                 \
            }                                                                  \
            CPA_COMMIT();                                                      \
        }

    const int a_row = ((lane >> 3) & 1) * 8 + (lane & 7);
    const int a_col = ((lane >> 4) & 1) * 16;
    const int b_row = ((lane >> 4) & 1) * 8 + (lane & 7);
    const int b_col = ((lane >> 3) & 1) * 16;

    FILL(0, 0);

    for (int it = 0; it < NKT; ++it) {
        if (it + 1 < NKT) FILL((it + 1) & 1, it + 1);
        if (it + 1 < NKT) CPA_WAIT1(); else CPA_WAIT0();
        __syncthreads();

        uint32_t stg = sb + (uint32_t)(it & 1) * STAGE_SZ;
        uint32_t A0b = stg, A1b = stg + 8192, B0b = stg + 16384, B1b = stg + 24576;

        #pragma unroll
        for (int ks = 0; ks < 2; ++ks) {
            const int kc = ks * 32;
            uint32_t a0f[2][4], a1f[2][4];
            #pragma unroll
            for (int mi = 0; mi < 2; ++mi) {
                LDSM4(a0f[mi], swadr(A0b, mw + mi * 16 + a_row, kc + a_col));
                LDSM4(a1f[mi], swadr(A1b, mw + mi * 16 + a_row, kc + a_col));
            }
            uint32_t b0f[8][2], b1f[8][2];
            #pragma unroll
            for (int nb = 0; nb < 4; ++nb) {
                uint32_t r4[4];
                LDSM4(r4, swadr(B0b, nw + nb * 16 + b_row, kc + b_col));
                b0f[nb*2][0] = r4[0]; b0f[nb*2][1] = r4[1];
                b0f[nb*2+1][0] = r4[2]; b0f[nb*2+1][1] = r4[3];
                LDSM4(r4, swadr(B1b, nw + nb * 16 + b_row, kc + b_col));
                b1f[nb*2][0] = r4[0]; b1f[nb*2][1] = r4[1];
                b1f[nb*2+1][0] = r4[2]; b1f[nb*2+1][1] = r4[3];
            }
            #pragma unroll
            for (int mi = 0; mi < 2; ++mi)
                #pragma unroll
                for (int nj = 0; nj < 8; ++nj)
                    MMA16816(acc[mi][nj], a0f[mi], b0f[nj]);
            #pragma unroll
            for (int mi = 0; mi < 2; ++mi)
                #pragma unroll
                for (int nj = 0; nj < 8; ++nj)
                    MMA16816(acc[mi][nj], a0f[mi], b1f[nj]);
            #pragma unroll
            for (int mi = 0; mi < 2; ++mi)
                #pragma unroll
                for (int nj = 0; nj < 8; ++nj)
                    MMA16816(acc[mi][nj], a1f[mi], b0f[nj]);
        }
        __syncthreads();
    }

    float* zp = g_zpart + ((size_t)kz * BATCH + m0) * NOUT;
    #pragma unroll
    for (int mi = 0; mi < 2; ++mi)
        #pragma unroll
        for (int nj = 0; nj < 8; ++nj) {
            int m = mw + mi * 16 + lr;
            int n = nw + nj * 8 + lc * 2;
            *(float2*)&zp[(size_t)m * NOUT + n] =
                make_float2(acc[mi][nj][0], acc[mi][nj][1]);
            *(float2*)&zp[(size_t)(m + 8) * NOUT + n] =
                make_float2(acc[mi][nj][2], acc[mi][nj][3]);
        }
}

// ---------------------------------------------------------------------------
// Kernel 3: reduce split-K partials + bias; mean | softplus(std)
// ---------------------------------------------------------------------------
__global__ __launch_bounds__(256) void epi_kernel(const float* __restrict__ bout,
                                                  float* __restrict__ out)
{
    int idx = blockIdx.x * 256 + threadIdx.x;
    if (idx >= BATCH * NOUT) return;
    int b = idx / NOUT, n = idx % NOUT;
    float s = bout[n];
    #pragma unroll
    for (int z = 0; z < KSPLIT; ++z)
        s += g_zpart[((size_t)z * BATCH + b) * NOUT + n];
    if (n < Z0) {
        out[(size_t)b * Z0 + n] = s;
    } else {
        float v = fmaxf(s, 0.f) + log1pf(expf(-fabsf(s)));   // stable softplus
        out[(size_t)BATCH * Z0 + (size_t)b * Z0 + (n - Z0)] = v;
    }
}

// ---------------------------------------------------------------------------
extern "C" void kernel_launch(void* const* d_in, const int* in_sizes, int n_in,
                              void* d_out, int out_size)
{
    const float* x    = (const float*)d_in[0];
    // d_in[1] = observed_tp (unused by the reference computation)
    const float* w1   = (const float*)d_in[2];
    const float* b1   = (const float*)d_in[3];
    const float* w2   = (const float*)d_in[4];
    const float* b2   = (const float*)d_in[5];
    const float* w3   = (const float*)d_in[6];
    const float* b3   = (const float*)d_in[7];
    const float* wout = (const float*)d_in[8];
    const float* bout = (const float*)d_in[9];
    float* out = (float*)d_out;

    cudaFuncSetAttribute(mma_gemm,
                         cudaFuncAttributeMaxDynamicSharedMemorySize, GEMM_SMEM);

    wconv_kernel<<<(NOUT * SIGCH + 255) / 256, 256>>>(wout);
    sig_kernel<<<BATCH, 512>>>(x, w1, b1, w2, b2, w3, b3);
    mma_gemm<<<dim3(BATCH / 128, KSPLIT), 256, GEMM_SMEM>>>();
    epi_kernel<<<(BATCH * NOUT + 255) / 256, 256>>>(bout, out);
}

// round 13
// speedup vs baseline: 1.0863x; 1.0863x over previous
#include <cuda_runtime.h>
#include <cuda_bf16.h>
#include <math.h>
#include <stdint.h>

#define BATCH 2048
#define LSEQ  70
#define DIN   15
#define HID   16
#define NF    4
#define KW    40
#define CDIM  20          // DIN + 1 + NF
#define LP    31          // LSEQ - KW + 1
#define Z0    64
#define NOUT  128         // 2*Z0
#define SIGCH 8420        // C + C^2 + C^3

#define KTOT   8640       // padded K (zero tail), 9*960
#define KSPLIT 9
#define KCHUNK 960
#define KB     32         // k per pipeline stage (bf16 elems)
#define NKT    (KCHUNK / KB)        // 30 iterations (single pass, all 3 terms)

typedef unsigned long long ull;

// Scratch (static device arrays; zero-initialized at load — padded K tail
// [8420,8640) is never written and stays zero)
__device__ __nv_bfloat16 g_a0[(size_t)BATCH * KTOT];   // sig hi
__device__ __nv_bfloat16 g_a1[(size_t)BATCH * KTOT];   // sig lo
__device__ __nv_bfloat16 g_b0[(size_t)NOUT * KTOT];    // wout hi
__device__ __nv_bfloat16 g_b1[(size_t)NOUT * KTOT];    // wout lo
__device__ float g_zpart[(size_t)KSPLIT * BATCH * NOUT];

// ---------------------------------------------------------------------------
// helpers
// ---------------------------------------------------------------------------
__device__ __forceinline__ uint32_t smem_u32(const void* p) {
    uint32_t a;
    asm("{ .reg .u64 t; cvta.to.shared.u64 t, %1; cvt.u32.u64 %0, t; }"
        : "=r"(a) : "l"(p));
    return a;
}
// 64B rows, 16B segs swizzled by seg ^ ((row>>1)&3)
__device__ __forceinline__ uint32_t swadr(uint32_t base, int row, int off) {
    return base + row * 64 + ((((off >> 4) ^ (row >> 1)) & 3) << 4) + (off & 15);
}
#define CPA16(dst, src) \
    asm volatile("cp.async.cg.shared.global [%0], [%1], 16;" :: "r"(dst), "l"(src))
#define CPA_COMMIT() asm volatile("cp.async.commit_group;" ::: "memory")
#define CPA_WAIT0()  asm volatile("cp.async.wait_group 0;" ::: "memory")
#define CPA_WAIT2()  asm volatile("cp.async.wait_group 2;" ::: "memory")

#define MMA16816(d, a, b) \
    asm volatile("mma.sync.aligned.m16n8k16.row.col.f32.bf16.bf16.f32 " \
        "{%0,%1,%2,%3}, {%4,%5,%6,%7}, {%8,%9}, {%0,%1,%2,%3};" \
        : "+f"((d)[0]), "+f"((d)[1]), "+f"((d)[2]), "+f"((d)[3]) \
        : "r"((a)[0]), "r"((a)[1]), "r"((a)[2]), "r"((a)[3]), \
          "r"((b)[0]), "r"((b)[1]))

#define LDSM4(r, addr) \
    asm volatile("ldmatrix.sync.aligned.m8n8.x4.shared.b16 {%0,%1,%2,%3}, [%4];" \
        : "=r"((r)[0]), "=r"((r)[1]), "=r"((r)[2]), "=r"((r)[3]) : "r"(addr))

// ---------------------------------------------------------------------------
// Kernel 1: per-batch path (conv chain) + depth-3 signature (proven R11
// 224-thread shape). Blocks [BATCH, BATCH+NOUT) instead convert one wout
// row to bf16 hi/lo (folds the old wconv kernel into this grid).
// ---------------------------------------------------------------------------
__global__ __launch_bounds__(224, 4) void sig_kernel(
    const float* __restrict__ x,    // (B, L, DIN)
    const float* __restrict__ w1,   // (HID, DIN, KW)
    const float* __restrict__ b1,
    const float* __restrict__ w2,   // (HID, HID)
    const float* __restrict__ b2,
    const float* __restrict__ w3,   // (NF, HID)
    const float* __restrict__ b3,
    const float* __restrict__ wout) // (NOUT, SIGCH)
{
    const int b = blockIdx.x;
    const int t = threadIdx.x;

    // ---- wout conversion blocks ----
    if (b >= BATCH) {
        int n = b - BATCH;
        const float* wr = wout + (size_t)n * SIGCH;
        __nv_bfloat16* o0 = g_b0 + (size_t)n * KTOT;
        __nv_bfloat16* o1 = g_b1 + (size_t)n * KTOT;
        for (int k = t; k < SIGCH; k += 224) {
            float v = wr[k];
            __nv_bfloat16 h = __float2bfloat16_rn(v);
            o0[k] = h;
            o1[k] = __float2bfloat16_rn(v - __bfloat162float(h));
        }
        return;
    }

    __shared__ float xs[(LSEQ + 1) * DIN];
    __shared__ float h1s[HID * LP];
    __shared__ float paths[LP * CDIM];
    __shared__ float h2s[HID * LP];
    __shared__ __align__(16) float dsm[LP * CDIM];
    __shared__ __align__(16) float w1s[HID * DIN * KW];  // 38.4 KB

    for (int i = t; i < LSEQ * DIN; i += 224) xs[i] = x[(size_t)b * LSEQ * DIN + i];
    if (t < DIN) xs[LSEQ * DIN + t] = 0.f;
    {
        const float4* w4 = (const float4*)w1;
        float4* s4 = (float4*)w1s;
        for (int i = t; i < HID * DIN * KW / 4; i += 224) s4[i] = w4[i];
    }
    __syncthreads();

    // ---- conv1 (VALID, kernel 40): 128 threads, sliding window ----
    if (t < 128) {
        const int o  = t >> 3;
        const int l0 = (t & 7) * 4;
        float a0 = 0.f, a1 = 0.f, a2 = 0.f, a3 = 0.f;
        const float* wrow = &w1s[o * DIN * KW];
        #pragma unroll 1
        for (int c = 0; c < DIN; ++c) {
            float xw0 = xs[(l0 + 0) * DIN + c];
            float xw1 = xs[(l0 + 1) * DIN + c];
            float xw2 = xs[(l0 + 2) * DIN + c];
            const float4* wc4 = (const float4*)(wrow + c * KW);
            #pragma unroll
            for (int kq = 0; kq < KW / 4; ++kq) {
                float4 w4 = wc4[kq];
                float xw3;
                xw3 = xs[(l0 + 4*kq + 3) * DIN + c];
                a0 = fmaf(w4.x, xw0, a0); a1 = fmaf(w4.x, xw1, a1);
                a2 = fmaf(w4.x, xw2, a2); a3 = fmaf(w4.x, xw3, a3);
                xw0 = xw1; xw1 = xw2; xw2 = xw3;
                xw3 = xs[(l0 + 4*kq + 4) * DIN + c];
                a0 = fmaf(w4.y, xw0, a0); a1 = fmaf(w4.y, xw1, a1);
                a2 = fmaf(w4.y, xw2, a2); a3 = fmaf(w4.y, xw3, a3);
                xw0 = xw1; xw1 = xw2; xw2 = xw3;
                xw3 = xs[(l0 + 4*kq + 5) * DIN + c];
                a0 = fmaf(w4.z, xw0, a0); a1 = fmaf(w4.z, xw1, a1);
                a2 = fmaf(w4.z, xw2, a2); a3 = fmaf(w4.z, xw3, a3);
                xw0 = xw1; xw1 = xw2; xw2 = xw3;
                xw3 = xs[(l0 + 4*kq + 6) * DIN + c];
                a0 = fmaf(w4.w, xw0, a0); a1 = fmaf(w4.w, xw1, a1);
                a2 = fmaf(w4.w, xw2, a2); a3 = fmaf(w4.w, xw3, a3);
                xw0 = xw1; xw1 = xw2; xw2 = xw3;
            }
        }
        float bias = b1[o];
        if (l0 + 0 < LP) h1s[o * LP + l0 + 0] = fmaxf(a0 + bias, 0.f);
        if (l0 + 1 < LP) h1s[o * LP + l0 + 1] = fmaxf(a1 + bias, 0.f);
        if (l0 + 2 < LP) h1s[o * LP + l0 + 2] = fmaxf(a2 + bias, 0.f);
        if (l0 + 3 < LP) h1s[o * LP + l0 + 3] = fmaxf(a3 + bias, 0.f);
    }
    __syncthreads();

    // ---- conv2 (1x1) + relu ----
    for (int idx = t; idx < HID * LP; idx += 224) {
        int o = idx / LP, l = idx % LP;
        float s = b2[o];
        #pragma unroll
        for (int c2 = 0; c2 < HID; ++c2)
            s = fmaf(w2[o * HID + c2], h1s[c2 * LP + l], s);
        h2s[idx] = fmaxf(s, 0.f);
    }
    __syncthreads();

    // ---- conv3 (1x1) + assemble path ----
    for (int idx = t; idx < LP * CDIM; idx += 224) {
        int l = idx / CDIM, c = idx % CDIM;
        float v;
        if (c < DIN) {
            v = xs[(KW - 1 + l) * DIN + c];
        } else if (c == DIN) {
            v = (float)l * (1.0f / (LP - 1));
        } else {
            int f = c - DIN - 1;
            float s = b3[f];
            #pragma unroll
            for (int c2 = 0; c2 < HID; ++c2)
                s = fmaf(w3[f * HID + c2], h2s[c2 * LP + l], s);
            v = s;
        }
        paths[idx] = v;
    }
    __syncthreads();

    for (int idx = t; idx < LP * CDIM; idx += 224) {
        int l = idx / CDIM;
        dsm[idx] = paths[idx] - (l ? paths[idx - CDIM] : 0.f);
    }
    __syncthreads();

    // ---- depth-3 signature (Chen), barrier-free scan ----
    const int i0 = t / CDIM;
    const int j0 = t % CDIM;
    float s1a = 0.f, s1b = 0.f, s2a = 0.f, s2b = 0.f;
    float s3a[CDIM], s3b[CDIM];
    #pragma unroll
    for (int k = 0; k < CDIM; ++k) { s3a[k] = 0.f; s3b[k] = 0.f; }

    if (t < 200) {
        #pragma unroll 2
        for (int s = 0; s < LP; ++s) {
            const float* dr = &dsm[s * CDIM];
            float dj  = dr[j0];
            float dia = dr[i0];
            float dib = dr[i0 + 10];
            float A0 = fmaf(dj, fmaf(dia, 1.f / 6.f, 0.5f * s1a), s2a);
            float A1 = fmaf(dj, fmaf(dib, 1.f / 6.f, 0.5f * s1b), s2b);
            s2a = fmaf(dj, fmaf(dia, 0.5f, s1a), s2a);
            s2b = fmaf(dj, fmaf(dib, 0.5f, s1b), s2b);
            s1a += dia;
            s1b += dib;
            const float4* dv4 = (const float4*)dr;
            #pragma unroll
            for (int q = 0; q < 5; ++q) {
                float4 dv = dv4[q];
                s3a[q*4+0] = fmaf(A0, dv.x, s3a[q*4+0]);
                s3a[q*4+1] = fmaf(A0, dv.y, s3a[q*4+1]);
                s3a[q*4+2] = fmaf(A0, dv.z, s3a[q*4+2]);
                s3a[q*4+3] = fmaf(A0, dv.w, s3a[q*4+3]);
                s3b[q*4+0] = fmaf(A1, dv.x, s3b[q*4+0]);
                s3b[q*4+1] = fmaf(A1, dv.y, s3b[q*4+1]);
                s3b[q*4+2] = fmaf(A1, dv.z, s3b[q*4+2]);
                s3b[q*4+3] = fmaf(A1, dv.w, s3b[q*4+3]);
            }
        }
    }

    // ---- write signature as bf16 hi/lo: [s1(20) | s2(400) | s3(8000)] ----
    size_t base = (size_t)b * KTOT;
    if (t < CDIM) {
        float v = paths[(LP - 1) * CDIM + t];      // s1 telescopes
        __nv_bfloat16 h = __float2bfloat16_rn(v);
        g_a0[base + t] = h;
        g_a1[base + t] = __float2bfloat16_rn(v - __bfloat162float(h));
    }
    if (t < 200) {
        {
            __nv_bfloat16 h = __float2bfloat16_rn(s2a);
            g_a0[base + CDIM + t] = h;
            g_a1[base + CDIM + t] = __float2bfloat16_rn(s2a - __bfloat162float(h));
            h = __float2bfloat16_rn(s2b);
            g_a0[base + CDIM + 200 + t] = h;
            g_a1[base + CDIM + 200 + t] = __float2bfloat16_rn(s2b - __bfloat162float(h));
        }
        size_t r0 = base + 420 + (size_t)t * CDIM;
        size_t r1 = base + 420 + (size_t)(t + 200) * CDIM;
        #pragma unroll
        for (int q = 0; q < 5; ++q) {
            ull h0 = 0, l0p = 0, h1 = 0, l1p = 0;
            #pragma unroll
            for (int j = 0; j < 4; ++j) {
                float va = s3a[q*4+j];
                __nv_bfloat16 h = __float2bfloat16_rn(va);
                __nv_bfloat16 l = __float2bfloat16_rn(va - __bfloat162float(h));
                h0  |= (ull)__bfloat16_as_ushort(h) << (16 * j);
                l0p |= (ull)__bfloat16_as_ushort(l) << (16 * j);
                float vb = s3b[q*4+j];
                h = __float2bfloat16_rn(vb);
                l = __float2bfloat16_rn(vb - __bfloat162float(h));
                h1  |= (ull)__bfloat16_as_ushort(h) << (16 * j);
                l1p |= (ull)__bfloat16_as_ushort(l) << (16 * j);
            }
            *(ull*)&g_a0[r0 + q * 4] = h0;
            *(ull*)&g_a1[r0 + q * 4] = l0p;
            *(ull*)&g_a0[r1 + q * 4] = h1;
            *(ull*)&g_a1[r1 + q * 4] = l1p;
        }
    }
}

// ---------------------------------------------------------------------------
// Kernel 2: mma.sync bf16 3-term GEMM, single pass over K, 3-stage pipeline.
// grid (16, 9): 128x128 block tile, 8 warps (warp tile 32x64).
// ---------------------------------------------------------------------------
#define STAGE_SZ 32768
#define GEMM_SMEM (3 * STAGE_SZ)

__global__ __launch_bounds__(256) void mma_gemm()
{
    extern __shared__ __align__(128) char smem[];
    const uint32_t sb = smem_u32(smem);

    const int t    = threadIdx.x;
    const int wid  = t >> 5;
    const int lane = t & 31;
    const int lr   = lane >> 2;       // 0..7
    const int lc   = lane & 3;        // 0..3
    const int mw   = (wid & 3) * 32;  // warp m offset
    const int nw   = (wid >> 2) * 64; // warp n offset
    const int m0   = blockIdx.x * 128;
    const int kz   = blockIdx.y;
    const int kbase = kz * KCHUNK;

    float acc[2][8][4];
    #pragma unroll
    for (int i = 0; i < 2; ++i)
        #pragma unroll
        for (int j = 0; j < 8; ++j)
            #pragma unroll
            for (int c = 0; c < 4; ++c) acc[i][j][c] = 0.f;

    #define FILL(bsel, kt)                                                     \
        {                                                                      \
            int k0 = kbase + (kt) * KB;                                        \
            uint32_t stg = sb + (uint32_t)(bsel) * STAGE_SZ;                   \
            _Pragma("unroll")                                                  \
            for (int i = 0; i < 8; ++i) {                                      \
                int id = t + i * 256;                                          \
                int sub = id >> 9, w = id & 511;                               \
                int row = w >> 2, seg = w & 3;                                 \
                uint32_t dst = stg + sub * 8192 + row * 64                     \
                               + ((seg ^ ((row >> 1) & 3)) << 4);              \
                const __nv_bfloat16* src;                                      \
                if (sub == 0)      src = g_a0 + (size_t)(m0 + row) * KTOT;     \
                else if (sub == 1) src = g_a1 + (size_t)(m0 + row) * KTOT;     \
                else if (sub == 2) src = g_b0 + (size_t)row * KTOT;            \
                else               src = g_b1 + (size_t)row * KTOT;            \
                CPA16(dst, (const char*)(src + k0 + seg * 8));                 \
            }                                                                  \
            CPA_COMMIT();                                                      \
        }

    const int a_row = ((lane >> 3) & 1) * 8 + (lane & 7);
    const int a_col = ((lane >> 4) & 1) * 16;
    const int b_row = ((lane >> 4) & 1) * 8 + (lane & 7);
    const int b_col = ((lane >> 3) & 1) * 16;

    FILL(0, 0);
    FILL(1, 1);

    int stage = 0;
    for (int it = 0; it < NKT; ++it) {
        if (it + 2 < NKT) { FILL((it + 2) % 3, it + 2); } else { CPA_COMMIT(); }
        CPA_WAIT2();                         // stage `it` complete
        __syncthreads();

        uint32_t stg = sb + (uint32_t)stage * STAGE_SZ;
        uint32_t A0b = stg, A1b = stg + 8192, B0b = stg + 16384, B1b = stg + 24576;

        #pragma unroll
        for (int ks = 0; ks < 2; ++ks) {
            const int kc = ks * 32;
            uint32_t a0f[2][4], a1f[2][4];
            #pragma unroll
            for (int mi = 0; mi < 2; ++mi) {
                LDSM4(a0f[mi], swadr(A0b, mw + mi * 16 + a_row, kc + a_col));
                LDSM4(a1f[mi], swadr(A1b, mw + mi * 16 + a_row, kc + a_col));
            }
            uint32_t b0f[8][2], b1f[8][2];
            #pragma unroll
            for (int nb = 0; nb < 4; ++nb) {
                uint32_t r4[4];
                LDSM4(r4, swadr(B0b, nw + nb * 16 + b_row, kc + b_col));
                b0f[nb*2][0] = r4[0]; b0f[nb*2][1] = r4[1];
                b0f[nb*2+1][0] = r4[2]; b0f[nb*2+1][1] = r4[3];
                LDSM4(r4, swadr(B1b, nw + nb * 16 + b_row, kc + b_col));
                b1f[nb*2][0] = r4[0]; b1f[nb*2][1] = r4[1];
                b1f[nb*2+1][0] = r4[2]; b1f[nb*2+1][1] = r4[3];
            }
            #pragma unroll
            for (int mi = 0; mi < 2; ++mi)
                #pragma unroll
                for (int nj = 0; nj < 8; ++nj)
                    MMA16816(acc[mi][nj], a0f[mi], b0f[nj]);
            #pragma unroll
            for (int mi = 0; mi < 2; ++mi)
                #pragma unroll
                for (int nj = 0; nj < 8; ++nj)
                    MMA16816(acc[mi][nj], a0f[mi], b1f[nj]);
            #pragma unroll
            for (int mi = 0; mi < 2; ++mi)
                #pragma unroll
                for (int nj = 0; nj < 8; ++nj)
                    MMA16816(acc[mi][nj], a1f[mi], b0f[nj]);
        }
        __syncthreads();
        stage = (stage + 1 == 3) ? 0 : stage + 1;
    }

    float* zp = g_zpart + ((size_t)kz * BATCH + m0) * NOUT;
    #pragma unroll
    for (int mi = 0; mi < 2; ++mi)
        #pragma unroll
        for (int nj = 0; nj < 8; ++nj) {
            int m = mw + mi * 16 + lr;
            int n = nw + nj * 8 + lc * 2;
            *(float2*)&zp[(size_t)m * NOUT + n] =
                make_float2(acc[mi][nj][0], acc[mi][nj][1]);
            *(float2*)&zp[(size_t)(m + 8) * NOUT + n] =
                make_float2(acc[mi][nj][2], acc[mi][nj][3]);
        }
}

// ---------------------------------------------------------------------------
// Kernel 3: reduce split-K partials + bias; mean | softplus(std)
// ---------------------------------------------------------------------------
__global__ __launch_bounds__(256) void epi_kernel(const float* __restrict__ bout,
                                                  float* __restrict__ out)
{
    int idx = blockIdx.x * 256 + threadIdx.x;
    if (idx >= BATCH * NOUT) return;
    int b = idx / NOUT, n = idx % NOUT;
    float s = bout[n];
    #pragma unroll
    for (int z = 0; z < KSPLIT; ++z)
        s += g_zpart[((size_t)z * BATCH + b) * NOUT + n];
    if (n < Z0) {
        out[(size_t)b * Z0 + n] = s;
    } else {
        float v = fmaxf(s, 0.f) + log1pf(expf(-fabsf(s)));   // stable softplus
        out[(size_t)BATCH * Z0 + (size_t)b * Z0 + (n - Z0)] = v;
    }
}

// ---------------------------------------------------------------------------
extern "C" void kernel_launch(void* const* d_in, const int* in_sizes, int n_in,
                              void* d_out, int out_size)
{
    const float* x    = (const float*)d_in[0];
    // d_in[1] = observed_tp (unused by the reference computation)
    const float* w1   = (const float*)d_in[2];
    const float* b1   = (const float*)d_in[3];
    const float* w2   = (const float*)d_in[4];
    const float* b2   = (const float*)d_in[5];
    const float* w3   = (const float*)d_in[6];
    const float* b3   = (const float*)d_in[7];
    const float* wout = (const float*)d_in[8];
    const float* bout = (const float*)d_in[9];
    float* out = (float*)d_out;

    cudaFuncSetAttribute(mma_gemm,
                         cudaFuncAttributeMaxDynamicSharedMemorySize, GEMM_SMEM);

    sig_kernel<<<BATCH + NOUT, 224>>>(x, w1, b1, w2, b2, w3, b3, wout);
    mma_gemm<<<dim3(BATCH / 128, KSPLIT), 256, GEMM_SMEM>>>();
    epi_kernel<<<(BATCH * NOUT + 255) / 256, 256>>>(bout, out);
}

// round 14
// speedup vs baseline: 1.6505x; 1.5194x over previous
#include <cuda_runtime.h>
#include <cuda_bf16.h>
#include <math.h>
#include <stdint.h>

#define BATCH 2048
#define LSEQ  70
#define DIN   15
#define HID   16
#define NF    4
#define KW    40
#define CDIM  20          // DIN + 1 + NF
#define LP    31          // LSEQ - KW + 1
#define Z0    64
#define NOUT  128         // 2*Z0
#define SIGCH 8420        // C + C^2 + C^3

#define KTOT   8640       // padded K (zero tail), 9*960
#define KSPLIT 9
#define KCHUNK 960
#define KB     32         // k per pipeline stage (bf16 elems)
#define NKT    (KCHUNK / KB)        // 30 iterations (single pass, all 3 terms)

typedef unsigned long long ull;

// Scratch (static device arrays; zero-initialized at load — padded K tail
// [8420,8640) is never written and stays zero)
__device__ __nv_bfloat16 g_a0[(size_t)BATCH * KTOT];   // sig hi
__device__ __nv_bfloat16 g_a1[(size_t)BATCH * KTOT];   // sig lo
__device__ __nv_bfloat16 g_b0[(size_t)NOUT * KTOT];    // wout hi
__device__ __nv_bfloat16 g_b1[(size_t)NOUT * KTOT];    // wout lo
__device__ float g_zpart[(size_t)KSPLIT * BATCH * NOUT];

// ---------------------------------------------------------------------------
// helpers
// ---------------------------------------------------------------------------
__device__ __forceinline__ uint32_t smem_u32(const void* p) {
    uint32_t a;
    asm("{ .reg .u64 t; cvta.to.shared.u64 t, %1; cvt.u32.u64 %0, t; }"
        : "=r"(a) : "l"(p));
    return a;
}
// 64B rows, 16B segs swizzled by seg ^ ((row>>1)&3)
__device__ __forceinline__ uint32_t swadr(uint32_t base, int row, int off) {
    return base + row * 64 + ((((off >> 4) ^ (row >> 1)) & 3) << 4) + (off & 15);
}
#define CPA16(dst, src) \
    asm volatile("cp.async.cg.shared.global [%0], [%1], 16;" :: "r"(dst), "l"(src))
#define CPA_COMMIT() asm volatile("cp.async.commit_group;" ::: "memory")
#define CPA_WAIT0()  asm volatile("cp.async.wait_group 0;" ::: "memory")
#define CPA_WAIT2()  asm volatile("cp.async.wait_group 2;" ::: "memory")

#define MMA16816(d, a, b) \
    asm volatile("mma.sync.aligned.m16n8k16.row.col.f32.bf16.bf16.f32 " \
        "{%0,%1,%2,%3}, {%4,%5,%6,%7}, {%8,%9}, {%0,%1,%2,%3};" \
        : "+f"((d)[0]), "+f"((d)[1]), "+f"((d)[2]), "+f"((d)[3]) \
        : "r"((a)[0]), "r"((a)[1]), "r"((a)[2]), "r"((a)[3]), \
          "r"((b)[0]), "r"((b)[1]))

#define LDSM4(r, addr) \
    asm volatile("ldmatrix.sync.aligned.m8n8.x4.shared.b16 {%0,%1,%2,%3}, [%4];" \
        : "=r"((r)[0]), "=r"((r)[1]), "=r"((r)[2]), "=r"((r)[3]) : "r"(addr))

// ---------------------------------------------------------------------------
// Kernel 1: per-batch path (conv chain) + depth-3 signature,
// emitting bf16 hi/lo split of the signature. (proven R11 version, verbatim)
// ---------------------------------------------------------------------------
__global__ __launch_bounds__(224, 4) void sig_kernel(
    const float* __restrict__ x,    // (B, L, DIN)
    const float* __restrict__ w1,   // (HID, DIN, KW)
    const float* __restrict__ b1,
    const float* __restrict__ w2,   // (HID, HID)
    const float* __restrict__ b2,
    const float* __restrict__ w3,   // (NF, HID)
    const float* __restrict__ b3)
{
    __shared__ float xs[(LSEQ + 1) * DIN];
    __shared__ float h1s[HID * LP];
    __shared__ float paths[LP * CDIM];
    __shared__ float h2s[HID * LP];
    __shared__ __align__(16) float dsm[LP * CDIM];
    __shared__ __align__(16) float w1s[HID * DIN * KW];  // 38.4 KB

    const int b = blockIdx.x;
    const int t = threadIdx.x;

    for (int i = t; i < LSEQ * DIN; i += 224) xs[i] = x[(size_t)b * LSEQ * DIN + i];
    if (t < DIN) xs[LSEQ * DIN + t] = 0.f;
    {
        const float4* w4 = (const float4*)w1;
        float4* s4 = (float4*)w1s;
        for (int i = t; i < HID * DIN * KW / 4; i += 224) s4[i] = w4[i];
    }
    __syncthreads();

    // ---- conv1 (VALID, kernel 40): 128 threads, sliding window ----
    if (t < 128) {
        const int o  = t >> 3;
        const int l0 = (t & 7) * 4;
        float a0 = 0.f, a1 = 0.f, a2 = 0.f, a3 = 0.f;
        const float* wrow = &w1s[o * DIN * KW];
        #pragma unroll 1
        for (int c = 0; c < DIN; ++c) {
            float xw0 = xs[(l0 + 0) * DIN + c];
            float xw1 = xs[(l0 + 1) * DIN + c];
            float xw2 = xs[(l0 + 2) * DIN + c];
            const float4* wc4 = (const float4*)(wrow + c * KW);
            #pragma unroll
            for (int kq = 0; kq < KW / 4; ++kq) {
                float4 w4 = wc4[kq];
                float xw3;
                xw3 = xs[(l0 + 4*kq + 3) * DIN + c];
                a0 = fmaf(w4.x, xw0, a0); a1 = fmaf(w4.x, xw1, a1);
                a2 = fmaf(w4.x, xw2, a2); a3 = fmaf(w4.x, xw3, a3);
                xw0 = xw1; xw1 = xw2; xw2 = xw3;
                xw3 = xs[(l0 + 4*kq + 4) * DIN + c];
                a0 = fmaf(w4.y, xw0, a0); a1 = fmaf(w4.y, xw1, a1);
                a2 = fmaf(w4.y, xw2, a2); a3 = fmaf(w4.y, xw3, a3);
                xw0 = xw1; xw1 = xw2; xw2 = xw3;
                xw3 = xs[(l0 + 4*kq + 5) * DIN + c];
                a0 = fmaf(w4.z, xw0, a0); a1 = fmaf(w4.z, xw1, a1);
                a2 = fmaf(w4.z, xw2, a2); a3 = fmaf(w4.z, xw3, a3);
                xw0 = xw1; xw1 = xw2; xw2 = xw3;
                xw3 = xs[(l0 + 4*kq + 6) * DIN + c];
                a0 = fmaf(w4.w, xw0, a0); a1 = fmaf(w4.w, xw1, a1);
                a2 = fmaf(w4.w, xw2, a2); a3 = fmaf(w4.w, xw3, a3);
                xw0 = xw1; xw1 = xw2; xw2 = xw3;
            }
        }
        float bias = b1[o];
        if (l0 + 0 < LP) h1s[o * LP + l0 + 0] = fmaxf(a0 + bias, 0.f);
        if (l0 + 1 < LP) h1s[o * LP + l0 + 1] = fmaxf(a1 + bias, 0.f);
        if (l0 + 2 < LP) h1s[o * LP + l0 + 2] = fmaxf(a2 + bias, 0.f);
        if (l0 + 3 < LP) h1s[o * LP + l0 + 3] = fmaxf(a3 + bias, 0.f);
    }
    __syncthreads();

    // ---- conv2 (1x1) + relu ----
    for (int idx = t; idx < HID * LP; idx += 224) {
        int o = idx / LP, l = idx % LP;
        float s = b2[o];
        #pragma unroll
        for (int c2 = 0; c2 < HID; ++c2)
            s = fmaf(w2[o * HID + c2], h1s[c2 * LP + l], s);
        h2s[idx] = fmaxf(s, 0.f);
    }
    __syncthreads();

    // ---- conv3 (1x1) + assemble path ----
    for (int idx = t; idx < LP * CDIM; idx += 224) {
        int l = idx / CDIM, c = idx % CDIM;
        float v;
        if (c < DIN) {
            v = xs[(KW - 1 + l) * DIN + c];
        } else if (c == DIN) {
            v = (float)l * (1.0f / (LP - 1));
        } else {
            int f = c - DIN - 1;
            float s = b3[f];
            #pragma unroll
            for (int c2 = 0; c2 < HID; ++c2)
                s = fmaf(w3[f * HID + c2], h2s[c2 * LP + l], s);
            v = s;
        }
        paths[idx] = v;
    }
    __syncthreads();

    for (int idx = t; idx < LP * CDIM; idx += 224) {
        int l = idx / CDIM;
        dsm[idx] = paths[idx] - (l ? paths[idx - CDIM] : 0.f);
    }
    __syncthreads();

    // ---- depth-3 signature (Chen), barrier-free scan ----
    const int i0 = t / CDIM;
    const int j0 = t % CDIM;
    float s1a = 0.f, s1b = 0.f, s2a = 0.f, s2b = 0.f;
    float s3a[CDIM], s3b[CDIM];
    #pragma unroll
    for (int k = 0; k < CDIM; ++k) { s3a[k] = 0.f; s3b[k] = 0.f; }

    if (t < 200) {
        #pragma unroll 2
        for (int s = 0; s < LP; ++s) {
            const float* dr = &dsm[s * CDIM];
            float dj  = dr[j0];
            float dia = dr[i0];
            float dib = dr[i0 + 10];
            float A0 = fmaf(dj, fmaf(dia, 1.f / 6.f, 0.5f * s1a), s2a);
            float A1 = fmaf(dj, fmaf(dib, 1.f / 6.f, 0.5f * s1b), s2b);
            s2a = fmaf(dj, fmaf(dia, 0.5f, s1a), s2a);
            s2b = fmaf(dj, fmaf(dib, 0.5f, s1b), s2b);
            s1a += dia;
            s1b += dib;
            const float4* dv4 = (const float4*)dr;
            #pragma unroll
            for (int q = 0; q < 5; ++q) {
                float4 dv = dv4[q];
                s3a[q*4+0] = fmaf(A0, dv.x, s3a[q*4+0]);
                s3a[q*4+1] = fmaf(A0, dv.y, s3a[q*4+1]);
                s3a[q*4+2] = fmaf(A0, dv.z, s3a[q*4+2]);
                s3a[q*4+3] = fmaf(A0, dv.w, s3a[q*4+3]);
                s3b[q*4+0] = fmaf(A1, dv.x, s3b[q*4+0]);
                s3b[q*4+1] = fmaf(A1, dv.y, s3b[q*4+1]);
                s3b[q*4+2] = fmaf(A1, dv.z, s3b[q*4+2]);
                s3b[q*4+3] = fmaf(A1, dv.w, s3b[q*4+3]);
            }
        }
    }

    // ---- write signature as bf16 hi/lo: [s1(20) | s2(400) | s3(8000)] ----
    size_t base = (size_t)b * KTOT;
    if (t < CDIM) {
        float v = paths[(LP - 1) * CDIM + t];      // s1 telescopes
        __nv_bfloat16 h = __float2bfloat16_rn(v);
        g_a0[base + t] = h;
        g_a1[base + t] = __float2bfloat16_rn(v - __bfloat162float(h));
    }
    if (t < 200) {
        {
            __nv_bfloat16 h = __float2bfloat16_rn(s2a);
            g_a0[base + CDIM + t] = h;
            g_a1[base + CDIM + t] = __float2bfloat16_rn(s2a - __bfloat162float(h));
            h = __float2bfloat16_rn(s2b);
            g_a0[base + CDIM + 200 + t] = h;
            g_a1[base + CDIM + 200 + t] = __float2bfloat16_rn(s2b - __bfloat162float(h));
        }
        size_t r0 = base + 420 + (size_t)t * CDIM;
        size_t r1 = base + 420 + (size_t)(t + 200) * CDIM;
        #pragma unroll
        for (int q = 0; q < 5; ++q) {
            ull h0 = 0, l0p = 0, h1 = 0, l1p = 0;
            #pragma unroll
            for (int j = 0; j < 4; ++j) {
                float va = s3a[q*4+j];
                __nv_bfloat16 h = __float2bfloat16_rn(va);
                __nv_bfloat16 l = __float2bfloat16_rn(va - __bfloat162float(h));
                h0  |= (ull)__bfloat16_as_ushort(h) << (16 * j);
                l0p |= (ull)__bfloat16_as_ushort(l) << (16 * j);
                float vb = s3b[q*4+j];
                h = __float2bfloat16_rn(vb);
                l = __float2bfloat16_rn(vb - __bfloat162float(h));
                h1  |= (ull)__bfloat16_as_ushort(h) << (16 * j);
                l1p |= (ull)__bfloat16_as_ushort(l) << (16 * j);
            }
            *(ull*)&g_a0[r0 + q * 4] = h0;
            *(ull*)&g_a1[r0 + q * 4] = l0p;
            *(ull*)&g_a0[r1 + q * 4] = h1;
            *(ull*)&g_a1[r1 + q * 4] = l1p;
        }
    }
}

// ---------------------------------------------------------------------------
// Kernel 1b: wout -> bf16 hi/lo split (padded to KTOT)
// ---------------------------------------------------------------------------
__global__ __launch_bounds__(256) void wconv_kernel(const float* __restrict__ wout)
{
    int i = blockIdx.x * 256 + threadIdx.x;
    if (i >= NOUT * SIGCH) return;
    int n = i / SIGCH, k = i % SIGCH;
    float v = wout[i];
    __nv_bfloat16 h = __float2bfloat16_rn(v);
    g_b0[(size_t)n * KTOT + k] = h;
    g_b1[(size_t)n * KTOT + k] = __float2bfloat16_rn(v - __bfloat162float(h));
}

// ---------------------------------------------------------------------------
// Kernel 2: mma.sync bf16 3-term GEMM, single pass over K, 3-stage pipeline.
// grid (16, 9): 128x128 block tile, 8 warps (warp tile 32x64).
// ---------------------------------------------------------------------------
#define STAGE_SZ 32768
#define GEMM_SMEM (3 * STAGE_SZ)

__global__ __launch_bounds__(256) void mma_gemm()
{
    extern __shared__ __align__(128) char smem[];
    const uint32_t sb = smem_u32(smem);

    const int t    = threadIdx.x;
    const int wid  = t >> 5;
    const int lane = t & 31;
    const int lr   = lane >> 2;       // 0..7
    const int lc   = lane & 3;        // 0..3
    const int mw   = (wid & 3) * 32;  // warp m offset
    const int nw   = (wid >> 2) * 64; // warp n offset
    const int m0   = blockIdx.x * 128;
    const int kz   = blockIdx.y;
    const int kbase = kz * KCHUNK;

    float acc[2][8][4];
    #pragma unroll
    for (int i = 0; i < 2; ++i)
        #pragma unroll
        for (int j = 0; j < 8; ++j)
            #pragma unroll
            for (int c = 0; c < 4; ++c) acc[i][j][c] = 0.f;

    #define FILL(bsel, kt)                                                     \
        {                                                                      \
            int k0 = kbase + (kt) * KB;                                        \
            uint32_t stg = sb + (uint32_t)(bsel) * STAGE_SZ;                   \
            _Pragma("unroll")                                                  \
            for (int i = 0; i < 8; ++i) {                                      \
                int id = t + i * 256;                                          \
                int sub = id >> 9, w = id & 511;                               \
                int row = w >> 2, seg = w & 3;                                 \
                uint32_t dst = stg + sub * 8192 + row * 64                     \
                               + ((seg ^ ((row >> 1) & 3)) << 4);              \
                const __nv_bfloat16* src;                                      \
                if (sub == 0)      src = g_a0 + (size_t)(m0 + row) * KTOT;     \
                else if (sub == 1) src = g_a1 + (size_t)(m0 + row) * KTOT;     \
                else if (sub == 2) src = g_b0 + (size_t)row * KTOT;            \
                else               src = g_b1 + (size_t)row * KTOT;            \
                CPA16(dst, (const char*)(src + k0 + seg * 8));                 \
            }                                                                  \
            CPA_COMMIT();                                                      \
        }

    const int a_row = ((lane >> 3) & 1) * 8 + (lane & 7);
    const int a_col = ((lane >> 4) & 1) * 16;
    const int b_row = ((lane >> 4) & 1) * 8 + (lane & 7);
    const int b_col = ((lane >> 3) & 1) * 16;

    FILL(0, 0);
    FILL(1, 1);

    for (int it = 0; it < NKT; ++it) {
        if (it + 2 < NKT) { FILL((it + 2) % 3, it + 2); } else { CPA_COMMIT(); }
        CPA_WAIT2();                         // stage `it` complete
        __syncthreads();

        uint32_t stg = sb + (uint32_t)(it % 3) * STAGE_SZ;
        uint32_t A0b = stg, A1b = stg + 8192, B0b = stg + 16384, B1b = stg + 24576;

        #pragma unroll
        for (int ks = 0; ks < 2; ++ks) {
            const int kc = ks * 32;
            uint32_t a0f[2][4], a1f[2][4];
            #pragma unroll
            for (int mi = 0; mi < 2; ++mi) {
                LDSM4(a0f[mi], swadr(A0b, mw + mi * 16 + a_row, kc + a_col));
                LDSM4(a1f[mi], swadr(A1b, mw + mi * 16 + a_row, kc + a_col));
            }
            uint32_t b0f[8][2], b1f[8][2];
            #pragma unroll
            for (int nb = 0; nb < 4; ++nb) {
                uint32_t r4[4];
                LDSM4(r4, swadr(B0b, nw + nb * 16 + b_row, kc + b_col));
                b0f[nb*2][0] = r4[0]; b0f[nb*2][1] = r4[1];
                b0f[nb*2+1][0] = r4[2]; b0f[nb*2+1][1] = r4[3];
                LDSM4(r4, swadr(B1b, nw + nb * 16 + b_row, kc + b_col));
                b1f[nb*2][0] = r4[0]; b1f[nb*2][1] = r4[1];
                b1f[nb*2+1][0] = r4[2]; b1f[nb*2+1][1] = r4[3];
            }
            #pragma unroll
            for (int mi = 0; mi < 2; ++mi)
                #pragma unroll
                for (int nj = 0; nj < 8; ++nj)
                    MMA16816(acc[mi][nj], a0f[mi], b0f[nj]);
            #pragma unroll
            for (int mi = 0; mi < 2; ++mi)
                #pragma unroll
                for (int nj = 0; nj < 8; ++nj)
                    MMA16816(acc[mi][nj], a0f[mi], b1f[nj]);
            #pragma unroll
            for (int mi = 0; mi < 2; ++mi)
                #pragma unroll
                for (int nj = 0; nj < 8; ++nj)
                    MMA16816(acc[mi][nj], a1f[mi], b0f[nj]);
        }
        __syncthreads();
    }

    float* zp = g_zpart + ((size_t)kz * BATCH + m0) * NOUT;
    #pragma unroll
    for (int mi = 0; mi < 2; ++mi)
        #pragma unroll
        for (int nj = 0; nj < 8; ++nj) {
            int m = mw + mi * 16 + lr;
            int n = nw + nj * 8 + lc * 2;
            *(float2*)&zp[(size_t)m * NOUT + n] =
                make_float2(acc[mi][nj][0], acc[mi][nj][1]);
            *(float2*)&zp[(size_t)(m + 8) * NOUT + n] =
                make_float2(acc[mi][nj][2], acc[mi][nj][3]);
        }
}

// ---------------------------------------------------------------------------
// Kernel 3: reduce split-K partials + bias; mean | softplus(std)
// ---------------------------------------------------------------------------
__global__ __launch_bounds__(256) void epi_kernel(const float* __restrict__ bout,
                                                  float* __restrict__ out)
{
    int idx = blockIdx.x * 256 + threadIdx.x;
    if (idx >= BATCH * NOUT) return;
    int b = idx / NOUT, n = idx % NOUT;
    float s = bout[n];
    #pragma unroll
    for (int z = 0; z < KSPLIT; ++z)
        s += g_zpart[((size_t)z * BATCH + b) * NOUT + n];
    if (n < Z0) {
        out[(size_t)b * Z0 + n] = s;
    } else {
        float v = fmaxf(s, 0.f) + log1pf(expf(-fabsf(s)));   // stable softplus
        out[(size_t)BATCH * Z0 + (size_t)b * Z0 + (n - Z0)] = v;
    }
}

// ---------------------------------------------------------------------------
extern "C" void kernel_launch(void* const* d_in, const int* in_sizes, int n_in,
                              void* d_out, int out_size)
{
    const float* x    = (const float*)d_in[0];
    // d_in[1] = observed_tp (unused by the reference computation)
    const float* w1   = (const float*)d_in[2];
    const float* b1   = (const float*)d_in[3];
    const float* w2   = (const float*)d_in[4];
    const float* b2   = (const float*)d_in[5];
    const float* w3   = (const float*)d_in[6];
    const float* b3   = (const float*)d_in[7];
    const float* wout = (const float*)d_in[8];
    const float* bout = (const float*)d_in[9];
    float* out = (float*)d_out;

    cudaFuncSetAttribute(mma_gemm,
                         cudaFuncAttributeMaxDynamicSharedMemorySize, GEMM_SMEM);

    wconv_kernel<<<(NOUT * SIGCH + 255) / 256, 256>>>(wout);
    sig_kernel<<<BATCH, 224>>>(x, w1, b1, w2, b2, w3, b3);
    mma_gemm<<<dim3(BATCH / 128, KSPLIT), 256, GEMM_SMEM>>>();
    epi_kernel<<<(BATCH * NOUT + 255) / 256, 256>>>(bout, out);
}

// round 15
// speedup vs baseline: 1.6770x; 1.0160x over previous
#include <cuda_runtime.h>
#include <cuda_bf16.h>
#include <math.h>
#include <stdint.h>

#define BATCH 2048
#define LSEQ  70
#define DIN   15
#define HID   16
#define NF    4
#define KW    40
#define CDIM  20          // DIN + 1 + NF
#define LP    31          // LSEQ - KW + 1
#define Z0    64
#define NOUT  128         // 2*Z0
#define SIGCH 8420        // C + C^2 + C^3

#define KTOT   8640       // padded K (zero tail), 9*960
#define KSPLIT 9
#define KCHUNK 960
#define KB     32         // k per pipeline stage (bf16 elems)
#define NKT    (KCHUNK / KB)        // 30 iterations (single pass, all 3 terms)

typedef unsigned long long ull;

// Scratch (static device arrays; zero-initialized at load — padded K tail
// [8420,8640) is never written and stays zero)
__device__ __nv_bfloat16 g_a0[(size_t)BATCH * KTOT];   // sig hi
__device__ __nv_bfloat16 g_a1[(size_t)BATCH * KTOT];   // sig lo
__device__ __nv_bfloat16 g_b0[(size_t)NOUT * KTOT];    // wout hi
__device__ __nv_bfloat16 g_b1[(size_t)NOUT * KTOT];    // wout lo
__device__ float g_zpart[(size_t)KSPLIT * BATCH * NOUT];

// ---------------------------------------------------------------------------
// helpers
// ---------------------------------------------------------------------------
__device__ __forceinline__ uint32_t smem_u32(const void* p) {
    uint32_t a;
    asm("{ .reg .u64 t; cvta.to.shared.u64 t, %1; cvt.u32.u64 %0, t; }"
        : "=r"(a) : "l"(p));
    return a;
}
// 64B rows, 16B segs swizzled by seg ^ ((row>>1)&3)
__device__ __forceinline__ uint32_t swadr(uint32_t base, int row, int off) {
    return base + row * 64 + ((((off >> 4) ^ (row >> 1)) & 3) << 4) + (off & 15);
}
#define CPA16(dst, src) \
    asm volatile("cp.async.cg.shared.global [%0], [%1], 16;" :: "r"(dst), "l"(src))
#define CPA_COMMIT() asm volatile("cp.async.commit_group;" ::: "memory")
#define CPA_WAIT2()  asm volatile("cp.async.wait_group 2;" ::: "memory")

#define MMA16816(d, a, b) \
    asm volatile("mma.sync.aligned.m16n8k16.row.col.f32.bf16.bf16.f32 " \
        "{%0,%1,%2,%3}, {%4,%5,%6,%7}, {%8,%9}, {%0,%1,%2,%3};" \
        : "+f"((d)[0]), "+f"((d)[1]), "+f"((d)[2]), "+f"((d)[3]) \
        : "r"((a)[0]), "r"((a)[1]), "r"((a)[2]), "r"((a)[3]), \
          "r"((b)[0]), "r"((b)[1]))

#define LDSM4(r, addr) \
    asm volatile("ldmatrix.sync.aligned.m8n8.x4.shared.b16 {%0,%1,%2,%3}, [%4];" \
        : "=r"((r)[0]), "=r"((r)[1]), "=r"((r)[2]), "=r"((r)[3]) : "r"(addr))

// ---------------------------------------------------------------------------
// Kernel 1: per-batch path (conv chain) + depth-3 signature,
// emitting bf16 hi/lo split of the signature. (proven R11 version, verbatim)
// ---------------------------------------------------------------------------
__global__ __launch_bounds__(224, 4) void sig_kernel(
    const float* __restrict__ x,    // (B, L, DIN)
    const float* __restrict__ w1,   // (HID, DIN, KW)
    const float* __restrict__ b1,
    const float* __restrict__ w2,   // (HID, HID)
    const float* __restrict__ b2,
    const float* __restrict__ w3,   // (NF, HID)
    const float* __restrict__ b3)
{
    __shared__ float xs[(LSEQ + 1) * DIN];
    __shared__ float h1s[HID * LP];
    __shared__ float paths[LP * CDIM];
    __shared__ float h2s[HID * LP];
    __shared__ __align__(16) float dsm[LP * CDIM];
    __shared__ __align__(16) float w1s[HID * DIN * KW];  // 38.4 KB

    const int b = blockIdx.x;
    const int t = threadIdx.x;

    for (int i = t; i < LSEQ * DIN; i += 224) xs[i] = x[(size_t)b * LSEQ * DIN + i];
    if (t < DIN) xs[LSEQ * DIN + t] = 0.f;
    {
        const float4* w4 = (const float4*)w1;
        float4* s4 = (float4*)w1s;
        for (int i = t; i < HID * DIN * KW / 4; i += 224) s4[i] = w4[i];
    }
    __syncthreads();

    // ---- conv1 (VALID, kernel 40): 128 threads, sliding window ----
    if (t < 128) {
        const int o  = t >> 3;
        const int l0 = (t & 7) * 4;
        float a0 = 0.f, a1 = 0.f, a2 = 0.f, a3 = 0.f;
        const float* wrow = &w1s[o * DIN * KW];
        #pragma unroll 1
        for (int c = 0; c < DIN; ++c) {
            float xw0 = xs[(l0 + 0) * DIN + c];
            float xw1 = xs[(l0 + 1) * DIN + c];
            float xw2 = xs[(l0 + 2) * DIN + c];
            const float4* wc4 = (const float4*)(wrow + c * KW);
            #pragma unroll
            for (int kq = 0; kq < KW / 4; ++kq) {
                float4 w4 = wc4[kq];
                float xw3;
                xw3 = xs[(l0 + 4*kq + 3) * DIN + c];
                a0 = fmaf(w4.x, xw0, a0); a1 = fmaf(w4.x, xw1, a1);
                a2 = fmaf(w4.x, xw2, a2); a3 = fmaf(w4.x, xw3, a3);
                xw0 = xw1; xw1 = xw2; xw2 = xw3;
                xw3 = xs[(l0 + 4*kq + 4) * DIN + c];
                a0 = fmaf(w4.y, xw0, a0); a1 = fmaf(w4.y, xw1, a1);
                a2 = fmaf(w4.y, xw2, a2); a3 = fmaf(w4.y, xw3, a3);
                xw0 = xw1; xw1 = xw2; xw2 = xw3;
                xw3 = xs[(l0 + 4*kq + 5) * DIN + c];
                a0 = fmaf(w4.z, xw0, a0); a1 = fmaf(w4.z, xw1, a1);
                a2 = fmaf(w4.z, xw2, a2); a3 = fmaf(w4.z, xw3, a3);
                xw0 = xw1; xw1 = xw2; xw2 = xw3;
                xw3 = xs[(l0 + 4*kq + 6) * DIN + c];
                a0 = fmaf(w4.w, xw0, a0); a1 = fmaf(w4.w, xw1, a1);
                a2 = fmaf(w4.w, xw2, a2); a3 = fmaf(w4.w, xw3, a3);
                xw0 = xw1; xw1 = xw2; xw2 = xw3;
            }
        }
        float bias = b1[o];
        if (l0 + 0 < LP) h1s[o * LP + l0 + 0] = fmaxf(a0 + bias, 0.f);
        if (l0 + 1 < LP) h1s[o * LP + l0 + 1] = fmaxf(a1 + bias, 0.f);
        if (l0 + 2 < LP) h1s[o * LP + l0 + 2] = fmaxf(a2 + bias, 0.f);
        if (l0 + 3 < LP) h1s[o * LP + l0 + 3] = fmaxf(a3 + bias, 0.f);
    }
    __syncthreads();

    // ---- conv2 (1x1) + relu ----
    for (int idx = t; idx < HID * LP; idx += 224) {
        int o = idx / LP, l = idx % LP;
        float s = b2[o];
        #pragma unroll
        for (int c2 = 0; c2 < HID; ++c2)
            s = fmaf(w2[o * HID + c2], h1s[c2 * LP + l], s);
        h2s[idx] = fmaxf(s, 0.f);
    }
    __syncthreads();

    // ---- conv3 (1x1) + assemble path ----
    for (int idx = t; idx < LP * CDIM; idx += 224) {
        int l = idx / CDIM, c = idx % CDIM;
        float v;
        if (c < DIN) {
            v = xs[(KW - 1 + l) * DIN + c];
        } else if (c == DIN) {
            v = (float)l * (1.0f / (LP - 1));
        } else {
            int f = c - DIN - 1;
            float s = b3[f];
            #pragma unroll
            for (int c2 = 0; c2 < HID; ++c2)
                s = fmaf(w3[f * HID + c2], h2s[c2 * LP + l], s);
            v = s;
        }
        paths[idx] = v;
    }
    __syncthreads();

    for (int idx = t; idx < LP * CDIM; idx += 224) {
        int l = idx / CDIM;
        dsm[idx] = paths[idx] - (l ? paths[idx - CDIM] : 0.f);
    }
    __syncthreads();

    // ---- depth-3 signature (Chen), barrier-free scan ----
    const int i0 = t / CDIM;
    const int j0 = t % CDIM;
    float s1a = 0.f, s1b = 0.f, s2a = 0.f, s2b = 0.f;
    float s3a[CDIM], s3b[CDIM];
    #pragma unroll
    for (int k = 0; k < CDIM; ++k) { s3a[k] = 0.f; s3b[k] = 0.f; }

    if (t < 200) {
        #pragma unroll 2
        for (int s = 0; s < LP; ++s) {
            const float* dr = &dsm[s * CDIM];
            float dj  = dr[j0];
            float dia = dr[i0];
            float dib = dr[i0 + 10];
            float A0 = fmaf(dj, fmaf(dia, 1.f / 6.f, 0.5f * s1a), s2a);
            float A1 = fmaf(dj, fmaf(dib, 1.f / 6.f, 0.5f * s1b), s2b);
            s2a = fmaf(dj, fmaf(dia, 0.5f, s1a), s2a);
            s2b = fmaf(dj, fmaf(dib, 0.5f, s1b), s2b);
            s1a += dia;
            s1b += dib;
            const float4* dv4 = (const float4*)dr;
            #pragma unroll
            for (int q = 0; q < 5; ++q) {
                float4 dv = dv4[q];
                s3a[q*4+0] = fmaf(A0, dv.x, s3a[q*4+0]);
                s3a[q*4+1] = fmaf(A0, dv.y, s3a[q*4+1]);
                s3a[q*4+2] = fmaf(A0, dv.z, s3a[q*4+2]);
                s3a[q*4+3] = fmaf(A0, dv.w, s3a[q*4+3]);
                s3b[q*4+0] = fmaf(A1, dv.x, s3b[q*4+0]);
                s3b[q*4+1] = fmaf(A1, dv.y, s3b[q*4+1]);
                s3b[q*4+2] = fmaf(A1, dv.z, s3b[q*4+2]);
                s3b[q*4+3] = fmaf(A1, dv.w, s3b[q*4+3]);
            }
        }
    }

    // ---- write signature as bf16 hi/lo: [s1(20) | s2(400) | s3(8000)] ----
    size_t base = (size_t)b * KTOT;
    if (t < CDIM) {
        float v = paths[(LP - 1) * CDIM + t];      // s1 telescopes
        __nv_bfloat16 h = __float2bfloat16_rn(v);
        g_a0[base + t] = h;
        g_a1[base + t] = __float2bfloat16_rn(v - __bfloat162float(h));
    }
    if (t < 200) {
        {
            __nv_bfloat16 h = __float2bfloat16_rn(s2a);
            g_a0[base + CDIM + t] = h;
            g_a1[base + CDIM + t] = __float2bfloat16_rn(s2a - __bfloat162float(h));
            h = __float2bfloat16_rn(s2b);
            g_a0[base + CDIM + 200 + t] = h;
            g_a1[base + CDIM + 200 + t] = __float2bfloat16_rn(s2b - __bfloat162float(h));
        }
        size_t r0 = base + 420 + (size_t)t * CDIM;
        size_t r1 = base + 420 + (size_t)(t + 200) * CDIM;
        #pragma unroll
        for (int q = 0; q < 5; ++q) {
            ull h0 = 0, l0p = 0, h1 = 0, l1p = 0;
            #pragma unroll
            for (int j = 0; j < 4; ++j) {
                float va = s3a[q*4+j];
                __nv_bfloat16 h = __float2bfloat16_rn(va);
                __nv_bfloat16 l = __float2bfloat16_rn(va - __bfloat162float(h));
                h0  |= (ull)__bfloat16_as_ushort(h) << (16 * j);
                l0p |= (ull)__bfloat16_as_ushort(l) << (16 * j);
                float vb = s3b[q*4+j];
                h = __float2bfloat16_rn(vb);
                l = __float2bfloat16_rn(vb - __bfloat162float(h));
                h1  |= (ull)__bfloat16_as_ushort(h) << (16 * j);
                l1p |= (ull)__bfloat16_as_ushort(l) << (16 * j);
            }
            *(ull*)&g_a0[r0 + q * 4] = h0;
            *(ull*)&g_a1[r0 + q * 4] = l0p;
            *(ull*)&g_a0[r1 + q * 4] = h1;
            *(ull*)&g_a1[r1 + q * 4] = l1p;
        }
    }
}

// ---------------------------------------------------------------------------
// Kernel 1b: wout -> bf16 hi/lo split (padded to KTOT)
// ---------------------------------------------------------------------------
__global__ __launch_bounds__(256) void wconv_kernel(const float* __restrict__ wout)
{
    int i = blockIdx.x * 256 + threadIdx.x;
    if (i >= NOUT * SIGCH) return;
    int n = i / SIGCH, k = i % SIGCH;
    float v = wout[i];
    __nv_bfloat16 h = __float2bfloat16_rn(v);
    g_b0[(size_t)n * KTOT + k] = h;
    g_b1[(size_t)n * KTOT + k] = __float2bfloat16_rn(v - __bfloat162float(h));
}

// ---------------------------------------------------------------------------
// Kernel 2: mma.sync bf16 3-term GEMM, single pass over K.
// 4-stage cp.async pipeline, ONE __syncthreads per iteration:
//   fill at iter `it` targets stage (it+3)&3 == (it-1)&3, whose compute
//   finished before this iteration's barrier (distance-3 prefetch).
// grid (16, 9): 128x128 block tile, 8 warps (warp tile 32x64).
// ---------------------------------------------------------------------------
#define STAGE_SZ 32768
#define NSTAGE   4
#define GEMM_SMEM (NSTAGE * STAGE_SZ)

__global__ __launch_bounds__(256) void mma_gemm()
{
    extern __shared__ __align__(128) char smem[];
    const uint32_t sb = smem_u32(smem);

    const int t    = threadIdx.x;
    const int wid  = t >> 5;
    const int lane = t & 31;
    const int lr   = lane >> 2;       // 0..7
    const int lc   = lane & 3;        // 0..3
    const int mw   = (wid & 3) * 32;  // warp m offset
    const int nw   = (wid >> 2) * 64; // warp n offset
    const int m0   = blockIdx.x * 128;
    const int kz   = blockIdx.y;
    const int kbase = kz * KCHUNK;

    float acc[2][8][4];
    #pragma unroll
    for (int i = 0; i < 2; ++i)
        #pragma unroll
        for (int j = 0; j < 8; ++j)
            #pragma unroll
            for (int c = 0; c < 4; ++c) acc[i][j][c] = 0.f;

    #define FILL(bsel, kt)                                                     \
        {                                                                      \
            int k0 = kbase + (kt) * KB;                                        \
            uint32_t stg = sb + (uint32_t)(bsel) * STAGE_SZ;                   \
            _Pragma("unroll")                                                  \
            for (int i = 0; i < 8; ++i) {                                      \
                int id = t + i * 256;                                          \
                int sub = id >> 9, w = id & 511;                               \
                int row = w >> 2, seg = w & 3;                                 \
                uint32_t dst = stg + sub * 8192 + row * 64                     \
                               + ((seg ^ ((row >> 1) & 3)) << 4);              \
                const __nv_bfloat16* src;                                      \
                if (sub == 0)      src = g_a0 + (size_t)(m0 + row) * KTOT;     \
                else if (sub == 1) src = g_a1 + (size_t)(m0 + row) * KTOT;     \
                else if (sub == 2) src = g_b0 + (size_t)row * KTOT;            \
                else               src = g_b1 + (size_t)row * KTOT;            \
                CPA16(dst, (const char*)(src + k0 + seg * 8));                 \
            }                                                                  \
            CPA_COMMIT();                                                      \
        }

    const int a_row = ((lane >> 3) & 1) * 8 + (lane & 7);
    const int a_col = ((lane >> 4) & 1) * 16;
    const int b_row = ((lane >> 4) & 1) * 8 + (lane & 7);
    const int b_col = ((lane >> 3) & 1) * 16;

    FILL(0, 0);
    FILL(1, 1);
    FILL(2, 2);

    for (int it = 0; it < NKT; ++it) {
        CPA_WAIT2();                 // 3 groups in flight -> group `it` done
        __syncthreads();             // all threads see stage it; stage it-1 compute done
        if (it + 3 < NKT) { FILL((it + 3) & 3, it + 3); } else { CPA_COMMIT(); }

        uint32_t stg = sb + (uint32_t)(it & 3) * STAGE_SZ;
        uint32_t A0b = stg, A1b = stg + 8192, B0b = stg + 16384, B1b = stg + 24576;

        #pragma unroll
        for (int ks = 0; ks < 2; ++ks) {
            const int kc = ks * 32;
            uint32_t a0f[2][4], a1f[2][4];
            #pragma unroll
            for (int mi = 0; mi < 2; ++mi) {
                LDSM4(a0f[mi], swadr(A0b, mw + mi * 16 + a_row, kc + a_col));
                LDSM4(a1f[mi], swadr(A1b, mw + mi * 16 + a_row, kc + a_col));
            }
            uint32_t b0f[8][2], b1f[8][2];
            #pragma unroll
            for (int nb = 0; nb < 4; ++nb) {
                uint32_t r4[4];
                LDSM4(r4, swadr(B0b, nw + nb * 16 + b_row, kc + b_col));
                b0f[nb*2][0] = r4[0]; b0f[nb*2][1] = r4[1];
                b0f[nb*2+1][0] = r4[2]; b0f[nb*2+1][1] = r4[3];
                LDSM4(r4, swadr(B1b, nw + nb * 16 + b_row, kc + b_col));
                b1f[nb*2][0] = r4[0]; b1f[nb*2][1] = r4[1];
                b1f[nb*2+1][0] = r4[2]; b1f[nb*2+1][1] = r4[3];
            }
            #pragma unroll
            for (int mi = 0; mi < 2; ++mi)
                #pragma unroll
                for (int nj = 0; nj < 8; ++nj)
                    MMA16816(acc[mi][nj], a0f[mi], b0f[nj]);
            #pragma unroll
            for (int mi = 0; mi < 2; ++mi)
                #pragma unroll
                for (int nj = 0; nj < 8; ++nj)
                    MMA16816(acc[mi][nj], a0f[mi], b1f[nj]);
            #pragma unroll
            for (int mi = 0; mi < 2; ++mi)
                #pragma unroll
                for (int nj = 0; nj < 8; ++nj)
                    MMA16816(acc[mi][nj], a1f[mi], b0f[nj]);
        }
    }

    float* zp = g_zpart + ((size_t)kz * BATCH + m0) * NOUT;
    #pragma unroll
    for (int mi = 0; mi < 2; ++mi)
        #pragma unroll
        for (int nj = 0; nj < 8; ++nj) {
            int m = mw + mi * 16 + lr;
            int n = nw + nj * 8 + lc * 2;
            *(float2*)&zp[(size_t)m * NOUT + n] =
                make_float2(acc[mi][nj][0], acc[mi][nj][1]);
            *(float2*)&zp[(size_t)(m + 8) * NOUT + n] =
                make_float2(acc[mi][nj][2], acc[mi][nj][3]);
        }
}

// ---------------------------------------------------------------------------
// Kernel 3: reduce split-K partials + bias; mean | softplus(std)
// ---------------------------------------------------------------------------
__global__ __launch_bounds__(256) void epi_kernel(const float* __restrict__ bout,
                                                  float* __restrict__ out)
{
    int idx = blockIdx.x * 256 + threadIdx.x;
    if (idx >= BATCH * NOUT) return;
    int b = idx / NOUT, n = idx % NOUT;
    float s = bout[n];
    #pragma unroll
    for (int z = 0; z < KSPLIT; ++z)
        s += g_zpart[((size_t)z * BATCH + b) * NOUT + n];
    if (n < Z0) {
        out[(size_t)b * Z0 + n] = s;
    } else {
        float v = fmaxf(s, 0.f) + log1pf(expf(-fabsf(s)));   // stable softplus
        out[(size_t)BATCH * Z0 + (size_t)b * Z0 + (n - Z0)] = v;
    }
}

// ---------------------------------------------------------------------------
extern "C" void kernel_launch(void* const* d_in, const int* in_sizes, int n_in,
                              void* d_out, int out_size)
{
    const float* x    = (const float*)d_in[0];
    // d_in[1] = observed_tp (unused by the reference computation)
    const float* w1   = (const float*)d_in[2];
    const float* b1   = (const float*)d_in[3];
    const float* w2   = (const float*)d_in[4];
    const float* b2   = (const float*)d_in[5];
    const float* w3   = (const float*)d_in[6];
    const float* b3   = (const float*)d_in[7];
    const float* wout = (const float*)d_in[8];
    const float* bout = (const float*)d_in[9];
    float* out = (float*)d_out;

    cudaFuncSetAttribute(mma_gemm,
                         cudaFuncAttributeMaxDynamicSharedMemorySize, GEMM_SMEM);

    wconv_kernel<<<(NOUT * SIGCH + 255) / 256, 256>>>(wout);
    sig_kernel<<<BATCH, 224>>>(x, w1, b1, w2, b2, w3, b3);
    mma_gemm<<<dim3(BATCH / 128, KSPLIT), 256, GEMM_SMEM>>>();
    epi_kernel<<<(BATCH * NOUT + 255) / 256, 256>>>(bout, out);
}